// round 3
// baseline (speedup 1.0000x reference)
#include <cuda_runtime.h>
#include <cuda_bf16.h>
#include <math.h>

// Problem dims (fixed per reference setup_inputs)
#define BB    8
#define NN    2048
#define LOW   512
#define HIGH  4096
#define BN    (BB*NN)          // 16384
#define BIGC  9.0e15f

// ---------------- scratch (allocation-free: __device__ globals) -------------
__device__ float g_Q [(long)BB*NN*LOW];     //  33.5 MB
__device__ float g_K [(long)BB*NN*HIGH];    // 268   MB
__device__ float g_V [(long)BB*NN*LOW];     //  33.5 MB
__device__ float g_E [(long)BB*LOW*HIGH];   //  67   MB
__device__ float g_A [(long)BB*LOW*HIGH];   //  67   MB
__device__ float g_X [(long)BB*NN*HIGH];    // 268   MB

// ---------------- generic tiled fp32 GEMM -----------------------------------
// C[b][m][n] = alpha * sum_k A[b][m][k] * B[b][n][k]  (+ bias[n])
// A element: Ab[(long)m*aM + (long)k*aK]; B element: Bb[(long)n*bN + (long)k*bK]
// AKC/BKC: operand is contiguous along k (aK==1 / bK==1); else contiguous along m/n.
#define TM 128
#define TN 128
#define TK 8
#define LDP 132   // padded shared row stride (floats)

template<bool AKC, bool BKC>
__global__ __launch_bounds__(256)
void gemm_kernel(const float* __restrict__ A, const float* __restrict__ B,
                 const float* __restrict__ bias, float* __restrict__ C,
                 int M, int Ncols, int Kd,
                 long aBatch, long bBatch, long cBatch,
                 int aM, int aK, int bN, int bK,
                 float alpha)
{
    __shared__ float As[TK * LDP];
    __shared__ float Bs[TK * LDP];

    const int bz = blockIdx.z;
    const float* Ab = A + (long)bz * aBatch;
    const float* Bb = B + (long)bz * bBatch;
    float*       Cb = C + (long)bz * cBatch;

    const int m0 = blockIdx.y * TM;
    const int n0 = blockIdx.x * TN;
    const int tid = threadIdx.x;
    const int tx = tid & 15;        // 0..15 -> 8 cols each
    const int ty = tid >> 4;        // 0..15 -> 8 rows each

    float acc[8][8];
#pragma unroll
    for (int i = 0; i < 8; i++)
#pragma unroll
        for (int j = 0; j < 8; j++) acc[i][j] = 0.0f;

    for (int k0 = 0; k0 < Kd; k0 += TK) {
        // ---- load A tile ----
        if (AKC) {
            // k contiguous: 128 rows x 2 float4
            int m  = tid >> 1;
            int kq = (tid & 1) * 4;
            float4 v = *(const float4*)(Ab + (long)(m0 + m) * aM + (k0 + kq));
            As[(kq + 0) * LDP + m] = v.x;
            As[(kq + 1) * LDP + m] = v.y;
            As[(kq + 2) * LDP + m] = v.z;
            As[(kq + 3) * LDP + m] = v.w;
        } else {
            // m contiguous: 8 k-rows x 32 float4
            int kq = tid >> 5;
            int m4 = (tid & 31) * 4;
            float4 v = *(const float4*)(Ab + (long)(k0 + kq) * aK + (m0 + m4));
            *(float4*)&As[kq * LDP + m4] = v;
        }
        // ---- load B tile ----
        if (BKC) {
            int n  = tid >> 1;
            int kq = (tid & 1) * 4;
            float4 v = *(const float4*)(Bb + (long)(n0 + n) * bN + (k0 + kq));
            Bs[(kq + 0) * LDP + n] = v.x;
            Bs[(kq + 1) * LDP + n] = v.y;
            Bs[(kq + 2) * LDP + n] = v.z;
            Bs[(kq + 3) * LDP + n] = v.w;
        } else {
            int kq = tid >> 5;
            int n4 = (tid & 31) * 4;
            float4 v = *(const float4*)(Bb + (long)(k0 + kq) * bK + (n0 + n4));
            *(float4*)&Bs[kq * LDP + n4] = v;
        }
        __syncthreads();

#pragma unroll
        for (int k = 0; k < TK; k++) {
            float a[8], b[8];
            *(float4*)&a[0] = *(const float4*)&As[k * LDP + ty * 8];
            *(float4*)&a[4] = *(const float4*)&As[k * LDP + ty * 8 + 4];
            *(float4*)&b[0] = *(const float4*)&Bs[k * LDP + tx * 8];
            *(float4*)&b[4] = *(const float4*)&Bs[k * LDP + tx * 8 + 4];
#pragma unroll
            for (int i = 0; i < 8; i++)
#pragma unroll
                for (int j = 0; j < 8; j++)
                    acc[i][j] = fmaf(a[i], b[j], acc[i][j]);
        }
        __syncthreads();
    }

    // ---- epilogue ----
    float bv[8] = {0.f,0.f,0.f,0.f,0.f,0.f,0.f,0.f};
    if (bias) {
        *(float4*)&bv[0] = *(const float4*)&bias[n0 + tx * 8];
        *(float4*)&bv[4] = *(const float4*)&bias[n0 + tx * 8 + 4];
    }
#pragma unroll
    for (int i = 0; i < 8; i++) {
        long base = (long)(m0 + ty * 8 + i) * Ncols + n0 + tx * 8;
        float4 o0, o1;
        o0.x = acc[i][0]*alpha + bv[0]; o0.y = acc[i][1]*alpha + bv[1];
        o0.z = acc[i][2]*alpha + bv[2]; o0.w = acc[i][3]*alpha + bv[3];
        o1.x = acc[i][4]*alpha + bv[4]; o1.y = acc[i][5]*alpha + bv[5];
        o1.z = acc[i][6]*alpha + bv[6]; o1.w = acc[i][7]*alpha + bv[7];
        *(float4*)&Cb[base]     = o0;
        *(float4*)&Cb[base + 4] = o1;
    }
}

// ---------------- fused dual softmax ----------------------------------------
// For each row (b,l) of e[B,LOW,HIGH]:
//   g = softmax(e)                                            (global)
//   local_e = mask ? (e-mn)/den : -BIG  (mn/mx over masked)   (min-max norm)
//   l = softmax(local_e)
//   attn = g + l
__device__ __forceinline__ float warpMaxF(float v){
#pragma unroll
    for (int o = 16; o; o >>= 1) v = fmaxf(v, __shfl_xor_sync(0xffffffffu, v, o));
    return v;
}
__device__ __forceinline__ float warpMinF(float v){
#pragma unroll
    for (int o = 16; o; o >>= 1) v = fminf(v, __shfl_xor_sync(0xffffffffu, v, o));
    return v;
}
__device__ __forceinline__ float warpSumF(float v){
#pragma unroll
    for (int o = 16; o; o >>= 1) v += __shfl_xor_sync(0xffffffffu, v, o);
    return v;
}

__global__ __launch_bounds__(256)
void attn_softmax_kernel(const float* __restrict__ e,
                         const int* __restrict__ linkage,
                         float* __restrict__ attn)
{
    const int l = blockIdx.x;
    const int b = blockIdx.y;
    const float* row = e + ((long)b * LOW + l) * HIGH;
    const int*   lk  = linkage + (long)l * HIGH;
    float* orow      = attn + ((long)b * LOW + l) * HIGH;

    const int tid  = threadIdx.x;
    const int lane = tid & 31;
    const int wid  = tid >> 5;

    float v[16];
    int   mk[16];
#pragma unroll
    for (int i = 0; i < 16; i++) {
        int h = tid + i * 256;
        v[i]  = row[h];
        mk[i] = lk[h];
    }

    // pass 1: global max, masked min, masked max
    float gmax = -INFINITY, mn = BIGC, mx = -BIGC;
#pragma unroll
    for (int i = 0; i < 16; i++) {
        gmax = fmaxf(gmax, v[i]);
        if (mk[i] > 0) { mn = fminf(mn, v[i]); mx = fmaxf(mx, v[i]); }
    }
    __shared__ float s0[8], s1[8], s2[8];
    gmax = warpMaxF(gmax); mn = warpMinF(mn); mx = warpMaxF(mx);
    if (lane == 0) { s0[wid] = gmax; s1[wid] = mn; s2[wid] = mx; }
    __syncthreads();
    gmax = -INFINITY; mn = BIGC; mx = -BIGC;
#pragma unroll
    for (int w = 0; w < 8; w++) {
        gmax = fmaxf(gmax, s0[w]); mn = fminf(mn, s1[w]); mx = fmaxf(mx, s2[w]);
    }
    __syncthreads();

    float den = mx - mn;
    if (den == 0.0f) den = 1e-6f;
    const bool any = (mn <= mx);                 // row has >=1 masked element
    const float lmax = any ? (mx - mn) / den : -BIGC;   // exact max of local_e

    // pass 2: exponentials + sums
    float ge[16], le[16];
    float gsum = 0.f, lsum = 0.f;
#pragma unroll
    for (int i = 0; i < 16; i++) {
        ge[i] = __expf(0.0f);   // placeholder avoided below
        ge[i] = expf(v[i] - gmax);
        gsum += ge[i];
        float loc = (mk[i] > 0) ? (v[i] - mn) / den : -BIGC;
        le[i] = expf(loc - lmax);
        lsum += le[i];
    }
    gsum = warpSumF(gsum); lsum = warpSumF(lsum);
    if (lane == 0) { s0[wid] = gsum; s1[wid] = lsum; }
    __syncthreads();
    gsum = 0.f; lsum = 0.f;
#pragma unroll
    for (int w = 0; w < 8; w++) { gsum += s0[w]; lsum += s1[w]; }

    const float gi = 1.0f / gsum;
    const float li = 1.0f / lsum;
#pragma unroll
    for (int i = 0; i < 16; i++)
        orow[tid + i * 256] = ge[i] * gi + le[i] * li;
}

// ---------------- launch ------------------------------------------------------
extern "C" void kernel_launch(void* const* d_in, const int* in_sizes, int n_in,
                              void* d_out, int out_size)
{
    const float* inputs = (const float*)d_in[0];
    const int*   linkage= (const int*)  d_in[1];
    const float* wq_w   = (const float*)d_in[2];
    const float* wq_b   = (const float*)d_in[3];
    const float* wk_w   = (const float*)d_in[4];
    const float* wk_b   = (const float*)d_in[5];
    const float* wv_w   = (const float*)d_in[6];
    const float* wv_b   = (const float*)d_in[7];
    const float* o_w    = (const float*)d_in[8];
    const float* o_b    = (const float*)d_in[9];
    float* out = (float*)d_out;

    float *Q, *K, *V, *E, *A, *X;
    cudaGetSymbolAddress((void**)&Q, g_Q);
    cudaGetSymbolAddress((void**)&K, g_K);
    cudaGetSymbolAddress((void**)&V, g_V);
    cudaGetSymbolAddress((void**)&E, g_E);
    cudaGetSymbolAddress((void**)&A, g_A);
    cudaGetSymbolAddress((void**)&X, g_X);

    // Q = inputs @ wq_w^T + wq_b   [16384,512]
    gemm_kernel<true,true><<<dim3(LOW/TN, BN/TM, 1), 256>>>(
        inputs, wq_w, wq_b, Q, BN, LOW, LOW,
        0, 0, 0, LOW, 1, LOW, 1, 1.0f);

    // K = inputs @ wk_w^T + wk_b   [16384,4096]
    gemm_kernel<true,true><<<dim3(HIGH/TN, BN/TM, 1), 256>>>(
        inputs, wk_w, wk_b, K, BN, HIGH, LOW,
        0, 0, 0, LOW, 1, LOW, 1, 1.0f);

    // V = inputs @ wv_w^T + wv_b   [16384,512]
    gemm_kernel<true,true><<<dim3(LOW/TN, BN/TM, 1), 256>>>(
        inputs, wv_w, wv_b, V, BN, LOW, LOW,
        0, 0, 0, LOW, 1, LOW, 1, 1.0f);

    // e[b] = (Q[b]^T @ K[b]) / sqrt(HIGH)   [8,512,4096], contraction over n=2048
    gemm_kernel<false,false><<<dim3(HIGH/TN, LOW/TM, BB), 256>>>(
        Q, K, nullptr, E, LOW, HIGH, NN,
        (long)NN*LOW, (long)NN*HIGH, (long)LOW*HIGH,
        1, LOW, 1, HIGH, 1.0f/64.0f);

    // attn = softmax_global(e) + softmax_local(minmaxnorm(e, mask))
    attn_softmax_kernel<<<dim3(LOW, BB), 256>>>(E, linkage, A);

    // x[b] = V[b] @ attn[b]   [8,2048,4096]
    gemm_kernel<true,false><<<dim3(HIGH/TN, NN/TM, BB), 256>>>(
        V, A, nullptr, X, NN, HIGH, LOW,
        (long)NN*LOW, (long)LOW*HIGH, (long)NN*HIGH,
        LOW, 1, 1, HIGH, 1.0f);

    // out = x @ o_w^T + o_b   [16384,4096]
    gemm_kernel<true,true><<<dim3(HIGH/TN, BN/TM, 1), 256>>>(
        X, o_w, o_b, out, BN, HIGH, HIGH,
        0, 0, 0, HIGH, 1, HIGH, 1, 1.0f);
}

// round 7
// speedup vs baseline: 3.1260x; 3.1260x over previous
#include <cuda_runtime.h>
#include <cstdint>
#include <math.h>

// Problem dims (fixed per reference setup_inputs)
#define BB    8
#define NN    2048
#define LOW   512
#define HIGH  4096
#define BN    (BB*NN)          // 16384
#define BIGC  9.0e15f

// ---------------- scratch (allocation-free: __device__ globals) -------------
__device__ float g_Q [(long)BB*NN*LOW];
__device__ float g_K [(long)BB*NN*HIGH];
__device__ float g_V [(long)BB*NN*LOW];
__device__ float g_E [(long)BB*LOW*HIGH];
__device__ float g_A [(long)BB*LOW*HIGH];
__device__ float g_X [(long)BB*NN*HIGH];

// ======================= helpers =============================================
__device__ __forceinline__ uint32_t tf32r(float x){   // round-to-nearest tf32
    uint32_t y; asm("cvt.rna.tf32.f32 %0, %1;" : "=r"(y) : "f"(x)); return y;
}

__device__ __forceinline__ void mma8(float* d, const uint32_t* a,
                                     uint32_t b0, uint32_t b1){
    asm volatile(
        "mma.sync.aligned.m16n8k8.row.col.f32.tf32.tf32.f32 "
        "{%0,%1,%2,%3}, {%4,%5,%6,%7}, {%8,%9}, {%0,%1,%2,%3};"
        : "+f"(d[0]), "+f"(d[1]), "+f"(d[2]), "+f"(d[3])
        : "r"(a[0]), "r"(a[1]), "r"(a[2]), "r"(a[3]), "r"(b0), "r"(b1));
}

// ======================= tile loaders ========================================
// SMEM tile: R rows x 32 k-floats, rows padded to PAD=36 (bank-conflict-free).
#define PAD 36

// K-contiguous source: elem(r,k) = src[r*ld + k]; src pre-offset to (row0,k0).
template<int R>
__device__ __forceinline__ void ldg_kc(float4* pf, const float* __restrict__ src,
                                       long ld, int tid){
#pragma unroll
    for (int it = 0; it < R/32; it++){
        int idx = tid + it * 256;
        int r = idx >> 3, kq = (idx & 7) << 2;
        pf[it] = *reinterpret_cast<const float4*>(src + (long)r * ld + kq);
    }
}
template<int R>
__device__ __forceinline__ void sts_kc(uint32_t* buf, const float4* pf, int tid){
#pragma unroll
    for (int it = 0; it < R/32; it++){
        int idx = tid + it * 256;
        int r = idx >> 3, kq = (idx & 7) << 2;
        uint4 v = { tf32r(pf[it].x), tf32r(pf[it].y), tf32r(pf[it].z), tf32r(pf[it].w) };
        *reinterpret_cast<uint4*>(buf + r * PAD + kq) = v;
    }
}
// MN-contiguous source (transpose at fill): elem(r,k) = src[k*ld + r];
// src pre-offset to (k0, row0). lane -> k, float4 along rows.
template<int R>
__device__ __forceinline__ void ldg_mn(float4* pf, const float* __restrict__ src,
                                       long ld, int tid){
    const int k = tid & 31, grp = tid >> 5;
#pragma unroll
    for (int it = 0; it < R/32; it++){
        int m4 = (grp + it * 8) << 2;
        pf[it] = *reinterpret_cast<const float4*>(src + (long)k * ld + m4);
    }
}
template<int R>
__device__ __forceinline__ void sts_mn(uint32_t* buf, const float4* pf, int tid){
    const int k = tid & 31, grp = tid >> 5;
#pragma unroll
    for (int it = 0; it < R/32; it++){
        int m4 = (grp + it * 8) << 2;
        uint32_t vv[4] = { tf32r(pf[it].x), tf32r(pf[it].y), tf32r(pf[it].z), tf32r(pf[it].w) };
#pragma unroll
        for (int j = 0; j < 4; j++) buf[(m4 + j) * PAD + k] = vv[j];
    }
}

// ======================= HMMA tf32 GEMM ======================================
// C[z](m,n) = alpha * sum_k A(m,k)*B(n,k) (+ bias[n])
// CTA tile 256x128, 8 warps (4m x 2n), warp tile 64x64, K-chunk 32,
// double-buffered smem + register prefetch of next chunk.
#define TMH 256
#define TNH 128
#define A_ST (TMH*PAD)               // 9216 floats
#define B_ST (TNH*PAD)               // 4608 floats
#define STG  (A_ST + B_ST)           // 13824 floats per stage
#define SMEM_HB (2*STG*4)            // 110592 bytes

template<bool AKC, bool BKC>
__global__ void __launch_bounds__(256, 1) mm_hmma(
    const float* __restrict__ A, const float* __restrict__ B,
    const float* __restrict__ bias, float* __restrict__ C,
    int Ncols, int Kd,
    long aB, long bB, long cB, long lda, long ldb, float alpha)
{
    extern __shared__ uint32_t sm[];
    const int tid  = threadIdx.x;
    const int lane = tid & 31;
    const int wid  = tid >> 5;
    const int g = lane >> 2, t = lane & 3;
    const int wm = (wid & 3) * 64;       // warp m-offset in CTA tile
    const int wn = (wid >> 2) * 64;      // warp n-offset

    const long m0 = (long)blockIdx.y * TMH;
    const long n0 = (long)blockIdx.x * TNH;
    const float* Ab = A + (long)blockIdx.z * aB;
    const float* Bb = B + (long)blockIdx.z * bB;
    float*       Cb = C + (long)blockIdx.z * cB;

    float4 pa[TMH/32], pb[TNH/32];
    // prefetch chunk 0
    if (AKC) ldg_kc<TMH>(pa, Ab + m0 * lda, lda, tid);
    else     ldg_mn<TMH>(pa, Ab + m0,       lda, tid);
    if (BKC) ldg_kc<TNH>(pb, Bb + n0 * ldb, ldb, tid);
    else     ldg_mn<TNH>(pb, Bb + n0,       ldb, tid);

    float acc[4][8][4];
#pragma unroll
    for (int mt = 0; mt < 4; mt++)
#pragma unroll
        for (int nt = 0; nt < 8; nt++)
#pragma unroll
            for (int j = 0; j < 4; j++) acc[mt][nt][j] = 0.0f;

    const int chunks = Kd >> 5;
    for (int i = 0; i < chunks; i++){
        uint32_t* sA = sm + (i & 1) * STG;
        uint32_t* sB = sA + A_ST;
        if (AKC) sts_kc<TMH>(sA, pa, tid); else sts_mn<TMH>(sA, pa, tid);
        if (BKC) sts_kc<TNH>(sB, pb, tid); else sts_mn<TNH>(sB, pb, tid);
        __syncthreads();

        if (i + 1 < chunks){
            long k0 = (long)(i + 1) << 5;
            if (AKC) ldg_kc<TMH>(pa, Ab + m0 * lda + k0, lda, tid);
            else     ldg_mn<TMH>(pa, Ab + k0 * lda + m0, lda, tid);
            if (BKC) ldg_kc<TNH>(pb, Bb + n0 * ldb + k0, ldb, tid);
            else     ldg_mn<TNH>(pb, Bb + k0 * ldb + n0, ldb, tid);
        }

#pragma unroll
        for (int ks = 0; ks < 4; ks++){
            const int kc = ks * 8;
            uint32_t a[4][4];
#pragma unroll
            for (int mt = 0; mt < 4; mt++){
                int rb = wm + mt * 16;
                a[mt][0] = sA[(rb + g    ) * PAD + kc + t    ];
                a[mt][1] = sA[(rb + g + 8) * PAD + kc + t    ];
                a[mt][2] = sA[(rb + g    ) * PAD + kc + t + 4];
                a[mt][3] = sA[(rb + g + 8) * PAD + kc + t + 4];
            }
#pragma unroll
            for (int nt = 0; nt < 8; nt++){
                int nb = wn + nt * 8;
                uint32_t b0 = sB[(nb + g) * PAD + kc + t    ];
                uint32_t b1 = sB[(nb + g) * PAD + kc + t + 4];
#pragma unroll
                for (int mt = 0; mt < 4; mt++) mma8(acc[mt][nt], a[mt], b0, b1);
            }
        }
        __syncthreads();
    }

    // ---------------- epilogue ------------------------------------------------
#pragma unroll
    for (int mt = 0; mt < 4; mt++){
        long r0 = m0 + wm + mt * 16 + g;
#pragma unroll
        for (int nt = 0; nt < 8; nt++){
            long c0 = n0 + wn + nt * 8 + 2 * t;
            float b0v = bias ? bias[c0]     : 0.0f;
            float b1v = bias ? bias[c0 + 1] : 0.0f;
            float2 o0 = { acc[mt][nt][0] * alpha + b0v, acc[mt][nt][1] * alpha + b1v };
            float2 o1 = { acc[mt][nt][2] * alpha + b0v, acc[mt][nt][3] * alpha + b1v };
            *reinterpret_cast<float2*>(Cb + r0 * (long)Ncols + c0)       = o0;
            *reinterpret_cast<float2*>(Cb + (r0 + 8) * (long)Ncols + c0) = o1;
        }
    }
}

// ======================= fused dual softmax ==================================
__device__ __forceinline__ float warpMaxF(float v){
#pragma unroll
    for (int o = 16; o; o >>= 1) v = fmaxf(v, __shfl_xor_sync(0xffffffffu, v, o));
    return v;
}
__device__ __forceinline__ float warpMinF(float v){
#pragma unroll
    for (int o = 16; o; o >>= 1) v = fminf(v, __shfl_xor_sync(0xffffffffu, v, o));
    return v;
}
__device__ __forceinline__ float warpSumF(float v){
#pragma unroll
    for (int o = 16; o; o >>= 1) v += __shfl_xor_sync(0xffffffffu, v, o);
    return v;
}

__global__ __launch_bounds__(256)
void attn_softmax_kernel(const float* __restrict__ e,
                         const int* __restrict__ linkage,
                         float* __restrict__ attn)
{
    const int l = blockIdx.x;
    const int b = blockIdx.y;
    const float* row = e + ((long)b * LOW + l) * HIGH;
    const int*   lk  = linkage + (long)l * HIGH;
    float* orow      = attn + ((long)b * LOW + l) * HIGH;

    const int tid  = threadIdx.x;
    const int lane = tid & 31;
    const int wid  = tid >> 5;

    float v[16];
    int   mk[16];
#pragma unroll
    for (int i = 0; i < 16; i++) {
        int h = tid + i * 256;
        v[i]  = row[h];
        mk[i] = lk[h];
    }

    float gmax = -INFINITY, mn = BIGC, mx = -BIGC;
#pragma unroll
    for (int i = 0; i < 16; i++) {
        gmax = fmaxf(gmax, v[i]);
        if (mk[i] > 0) { mn = fminf(mn, v[i]); mx = fmaxf(mx, v[i]); }
    }
    __shared__ float s0[8], s1[8], s2[8];
    gmax = warpMaxF(gmax); mn = warpMinF(mn); mx = warpMaxF(mx);
    if (lane == 0) { s0[wid] = gmax; s1[wid] = mn; s2[wid] = mx; }
    __syncthreads();
    gmax = -INFINITY; mn = BIGC; mx = -BIGC;
#pragma unroll
    for (int w = 0; w < 8; w++) {
        gmax = fmaxf(gmax, s0[w]); mn = fminf(mn, s1[w]); mx = fmaxf(mx, s2[w]);
    }
    __syncthreads();

    float den = mx - mn;
    if (den == 0.0f) den = 1e-6f;
    const bool any = (mn <= mx);
    const float lmax = any ? (mx - mn) / den : -BIGC;

    float ge[16], le[16];
    float gsum = 0.f, lsum = 0.f;
#pragma unroll
    for (int i = 0; i < 16; i++) {
        ge[i] = expf(v[i] - gmax);
        gsum += ge[i];
        float loc = (mk[i] > 0) ? (v[i] - mn) / den : -BIGC;
        le[i] = expf(loc - lmax);
        lsum += le[i];
    }
    gsum = warpSumF(gsum); lsum = warpSumF(lsum);
    if (lane == 0) { s0[wid] = gsum; s1[wid] = lsum; }
    __syncthreads();
    gsum = 0.f; lsum = 0.f;
#pragma unroll
    for (int w = 0; w < 8; w++) { gsum += s0[w]; lsum += s1[w]; }

    const float gi = 1.0f / gsum;
    const float li = 1.0f / lsum;
#pragma unroll
    for (int i = 0; i < 16; i++)
        orow[tid + i * 256] = ge[i] * gi + le[i] * li;
}

// ======================= launch ==============================================
extern "C" void kernel_launch(void* const* d_in, const int* in_sizes, int n_in,
                              void* d_out, int out_size)
{
    const float* inputs = (const float*)d_in[0];
    const int*   linkage= (const int*)  d_in[1];
    const float* wq_w   = (const float*)d_in[2];
    const float* wq_b   = (const float*)d_in[3];
    const float* wk_w   = (const float*)d_in[4];
    const float* wk_b   = (const float*)d_in[5];
    const float* wv_w   = (const float*)d_in[6];
    const float* wv_b   = (const float*)d_in[7];
    const float* o_w    = (const float*)d_in[8];
    const float* o_b    = (const float*)d_in[9];
    float* out = (float*)d_out;

    float *Q, *K, *V, *E, *Aat, *X;
    cudaGetSymbolAddress((void**)&Q,   g_Q);
    cudaGetSymbolAddress((void**)&K,   g_K);
    cudaGetSymbolAddress((void**)&V,   g_V);
    cudaGetSymbolAddress((void**)&E,   g_E);
    cudaGetSymbolAddress((void**)&Aat, g_A);
    cudaGetSymbolAddress((void**)&X,   g_X);

    cudaFuncSetAttribute(mm_hmma<true,true>,
                         cudaFuncAttributeMaxDynamicSharedMemorySize, SMEM_HB);
    cudaFuncSetAttribute(mm_hmma<false,false>,
                         cudaFuncAttributeMaxDynamicSharedMemorySize, SMEM_HB);
    cudaFuncSetAttribute(mm_hmma<true,false>,
                         cudaFuncAttributeMaxDynamicSharedMemorySize, SMEM_HB);

    // Q = inputs @ wq_w^T + wq_b     [16384, 512]
    mm_hmma<true,true><<<dim3(LOW/TNH, BN/TMH, 1), 256, SMEM_HB>>>(
        inputs, wq_w, wq_b, Q, LOW, LOW, 0, 0, 0, LOW, LOW, 1.0f);

    // K = inputs @ wk_w^T + wk_b     [16384, 4096]
    mm_hmma<true,true><<<dim3(HIGH/TNH, BN/TMH, 1), 256, SMEM_HB>>>(
        inputs, wk_w, wk_b, K, HIGH, LOW, 0, 0, 0, LOW, LOW, 1.0f);

    // V = inputs @ wv_w^T + wv_b     [16384, 512]
    mm_hmma<true,true><<<dim3(LOW/TNH, BN/TMH, 1), 256, SMEM_HB>>>(
        inputs, wv_w, wv_b, V, LOW, LOW, 0, 0, 0, LOW, LOW, 1.0f);

    // e[b] = (Q[b]^T @ K[b]) / 64    [8, 512, 4096], contraction over n=2048
    mm_hmma<false,false><<<dim3(HIGH/TNH, LOW/TMH, BB), 256, SMEM_HB>>>(
        Q, K, nullptr, E, HIGH, NN,
        (long)NN*LOW, (long)NN*HIGH, (long)LOW*HIGH, LOW, HIGH, 1.0f/64.0f);

    // attn = softmax_global(e) + softmax_local(minmaxnorm(e, mask))
    attn_softmax_kernel<<<dim3(LOW, BB), 256>>>(E, linkage, Aat);

    // x[b] = V[b] @ attn[b]          [8, 2048, 4096]
    mm_hmma<true,false><<<dim3(HIGH/TNH, NN/TMH, BB), 256, SMEM_HB>>>(
        V, Aat, nullptr, X, HIGH, LOW,
        (long)NN*LOW, (long)LOW*HIGH, (long)NN*HIGH, LOW, HIGH, 1.0f);

    // out = x @ o_w^T + o_b          [16384, 4096]
    mm_hmma<true,true><<<dim3(HIGH/TNH, BN/TMH, 1), 256, SMEM_HB>>>(
        X, o_w, o_b, out, HIGH, HIGH, 0, 0, 0, HIGH, HIGH, 1.0f);
}

// round 9
// speedup vs baseline: 3.5154x; 1.1246x over previous
#include <cuda_runtime.h>
#include <cstdint>
#include <math.h>

// Problem dims (fixed per reference setup_inputs)
#define BB    8
#define NN    2048
#define LOW   512
#define HIGH  4096
#define BN    (BB*NN)          // 16384
#define BIGC  9.0e15f

// ---------------- scratch (allocation-free: __device__ globals) -------------
__device__ float g_Q [(long)BB*NN*LOW];
__device__ float g_K [(long)BB*NN*HIGH];
__device__ float g_V [(long)BB*NN*LOW];
__device__ float g_E [(long)BB*LOW*HIGH];
__device__ float g_A [(long)BB*LOW*HIGH];
__device__ float g_X [(long)BB*NN*HIGH];
// tf32-pre-rounded copies of inputs/weights (enables raw cp.async loads)
__device__ float g_RI [(long)BN*LOW];        // inputs   [16384,512]
__device__ float g_Wq [(long)LOW*LOW];       // wq_w     [512,512]
__device__ float g_Wk [(long)HIGH*LOW];      // wk_w     [4096,512]
__device__ float g_Wv [(long)LOW*LOW];       // wv_w     [512,512]
__device__ float g_Wo [(long)HIGH*HIGH];     // o_w      [4096,4096]

// ======================= helpers =============================================
__device__ __forceinline__ uint32_t tf32r(float x){   // round-to-nearest tf32
    uint32_t y; asm("cvt.rna.tf32.f32 %0, %1;" : "=r"(y) : "f"(x)); return y;
}
__device__ __forceinline__ uint32_t smem_u32(const void* p){
    uint32_t a;
    asm("{ .reg .u64 t; cvta.to.shared.u64 t, %1; cvt.u32.u64 %0, t; }" : "=r"(a) : "l"(p));
    return a;
}
__device__ __forceinline__ void cpa16(uint32_t dst, const float* src){
    asm volatile("cp.async.cg.shared.global [%0], [%1], 16;" :: "r"(dst), "l"(src));
}
__device__ __forceinline__ void mma8(float* d, const uint32_t* a,
                                     uint32_t b0, uint32_t b1){
    asm volatile(
        "mma.sync.aligned.m16n8k8.row.col.f32.tf32.tf32.f32 "
        "{%0,%1,%2,%3}, {%4,%5,%6,%7}, {%8,%9}, {%0,%1,%2,%3};"
        : "+f"(d[0]), "+f"(d[1]), "+f"(d[2]), "+f"(d[3])
        : "r"(a[0]), "r"(a[1]), "r"(a[2]), "r"(a[3]), "r"(b0), "r"(b1));
}

// ======================= pre-rounding pass ===================================
__global__ __launch_bounds__(256)
void round_kernel(const float* __restrict__ s, float* __restrict__ d, long n4){
    long i = (long)blockIdx.x * 256 + threadIdx.x;
    if (i < n4){
        float4 v = reinterpret_cast<const float4*>(s)[i];
        float4 o;
        o.x = __uint_as_float(tf32r(v.x));
        o.y = __uint_as_float(tf32r(v.y));
        o.z = __uint_as_float(tf32r(v.z));
        o.w = __uint_as_float(tf32r(v.w));
        reinterpret_cast<float4*>(d)[i] = o;
    }
}

// ======================= HMMA tf32 GEMM ======================================
// C[z](m,n) = alpha * sum_k A(m,k)*B(n,k) (+ bias[n]) [optionally tf32-rounded]
// CTA tile 256x128, 512 threads = 16 warps (4m x 4n), warp tile 64x32.
// 3-stage cp.async pipeline, K-chunk 32. Inputs already tf32-rounded in gmem.
// AMN/BMN: operand stored MN-major (contiguous in m/n); loaded raw, fragments
// indexed transposed. Pads: 36,264,136 == 4,8,8 (mod 32) -> conflict-free LDS.
#define TM 256
#define TN 128
#define PADK  36
#define PADAM 264           // 256+8
#define PADBM 136           // 128+8
#define A_FL  9216          // floats: max(256*36, 32*264)
#define B_FL  4608          // floats: max(128*36, 32*136)
#define STG_FL (A_FL + B_FL)       // 13824 floats = 55296 B
#define SMEM_BYTES (3*STG_FL*4)    // 165888 B

template<bool AMN, bool BMN>
__global__ void __launch_bounds__(512, 1) mm_tc(
    const float* __restrict__ A, const float* __restrict__ B,
    const float* __restrict__ bias, float* __restrict__ C,
    int Ncols, int Kd, long aB, long bB, long cB,
    long lda, long ldb, float alpha, int roundC)
{
    extern __shared__ float sm[];
    const uint32_t smb = smem_u32(sm);
    const int tid  = threadIdx.x;
    const int lane = tid & 31;
    const int wid  = tid >> 5;
    const int g = lane >> 2, t = lane & 3;
    const int wm = (wid & 3) * 64;
    const int wn = (wid >> 2) * 32;
    const long m0 = (long)blockIdx.y * TM;
    const long n0 = (long)blockIdx.x * TN;
    const float* Ab = A + (long)blockIdx.z * aB;
    const float* Bb = B + (long)blockIdx.z * bB;
    float*       Cb = C + (long)blockIdx.z * cB;
    const int chunks = Kd >> 5;

    auto fill = [&](int ch, int s){
        uint32_t dA = smb + (uint32_t)(s * STG_FL) * 4u;
        uint32_t dB = dA + (uint32_t)A_FL * 4u;
        const long k0 = (long)ch << 5;
        if (AMN){
            const float* src = Ab + k0 * lda + m0;
#pragma unroll
            for (int it = 0; it < 4; it++){
                int idx = tid + it * 512;
                int r = idx >> 6, seg = (idx & 63) << 2;
                cpa16(dA + (uint32_t)(r * PADAM + seg) * 4u, src + (long)r * lda + seg);
            }
        } else {
            const float* src = Ab + m0 * lda + k0;
#pragma unroll
            for (int it = 0; it < 4; it++){
                int idx = tid + it * 512;
                int r = idx >> 3, seg = (idx & 7) << 2;
                cpa16(dA + (uint32_t)(r * PADK + seg) * 4u, src + (long)r * lda + seg);
            }
        }
        if (BMN){
            const float* src = Bb + k0 * ldb + n0;
#pragma unroll
            for (int it = 0; it < 2; it++){
                int idx = tid + it * 512;
                int r = idx >> 5, seg = (idx & 31) << 2;
                cpa16(dB + (uint32_t)(r * PADBM + seg) * 4u, src + (long)r * ldb + seg);
            }
        } else {
            const float* src = Bb + n0 * ldb + k0;
#pragma unroll
            for (int it = 0; it < 2; it++){
                int idx = tid + it * 512;
                int r = idx >> 3, seg = (idx & 7) << 2;
                cpa16(dB + (uint32_t)(r * PADK + seg) * 4u, src + (long)r * ldb + seg);
            }
        }
    };

    fill(0, 0); asm volatile("cp.async.commit_group;" ::: "memory");
    fill(1, 1); asm volatile("cp.async.commit_group;" ::: "memory");

    float acc[4][4][4];
#pragma unroll
    for (int mt = 0; mt < 4; mt++)
#pragma unroll
        for (int nt = 0; nt < 4; nt++)
#pragma unroll
            for (int j = 0; j < 4; j++) acc[mt][nt][j] = 0.0f;

    // fragment base offsets (float indices within stage)
    int baA[4], baB[4];
#pragma unroll
    for (int mt = 0; mt < 4; mt++)
        baA[mt] = AMN ? (t * PADAM + wm + mt * 16 + g)
                      : ((wm + mt * 16 + g) * PADK + t);
#pragma unroll
    for (int nt = 0; nt < 4; nt++)
        baB[nt] = BMN ? (t * PADBM + wn + nt * 8 + g)
                      : ((wn + nt * 8 + g) * PADK + t);
    const int aks = AMN ? 8 * PADAM : 8;      // +8 in k
    const int a1o = AMN ? 8 : 8 * PADK;       // +8 in m
    const int a2o = AMN ? 4 * PADAM : 4;      // +4 in k
    const int bks = BMN ? 8 * PADBM : 8;
    const int b1o = BMN ? 4 * PADBM : 4;

    for (int i = 0; i < chunks; i++){
        asm volatile("cp.async.wait_group 1;" ::: "memory");
        __syncthreads();
        if (i + 2 < chunks) fill(i + 2, (i + 2) % 3);
        asm volatile("cp.async.commit_group;" ::: "memory");

        const uint32_t* sA = reinterpret_cast<const uint32_t*>(sm + (i % 3) * STG_FL);
        const uint32_t* sB = sA + A_FL;
#pragma unroll
        for (int ks = 0; ks < 4; ks++){
            uint32_t a[4][4], b[4][2];
#pragma unroll
            for (int mt = 0; mt < 4; mt++){
                int o = baA[mt] + ks * aks;
                a[mt][0] = sA[o];           a[mt][1] = sA[o + a1o];
                a[mt][2] = sA[o + a2o];     a[mt][3] = sA[o + a1o + a2o];
            }
#pragma unroll
            for (int nt = 0; nt < 4; nt++){
                int o = baB[nt] + ks * bks;
                b[nt][0] = sB[o];           b[nt][1] = sB[o + b1o];
            }
#pragma unroll
            for (int nt = 0; nt < 4; nt++)
#pragma unroll
                for (int mt = 0; mt < 4; mt++)
                    mma8(acc[mt][nt], a[mt], b[nt][0], b[nt][1]);
        }
    }

    // ---------------- epilogue ------------------------------------------------
#pragma unroll
    for (int mt = 0; mt < 4; mt++){
        long r0 = m0 + wm + mt * 16 + g;
#pragma unroll
        for (int nt = 0; nt < 4; nt++){
            long c0 = n0 + wn + nt * 8 + 2 * t;
            float b0v = bias ? bias[c0]     : 0.0f;
            float b1v = bias ? bias[c0 + 1] : 0.0f;
            float v00 = acc[mt][nt][0] * alpha + b0v;
            float v01 = acc[mt][nt][1] * alpha + b1v;
            float v10 = acc[mt][nt][2] * alpha + b0v;
            float v11 = acc[mt][nt][3] * alpha + b1v;
            if (roundC){
                v00 = __uint_as_float(tf32r(v00));
                v01 = __uint_as_float(tf32r(v01));
                v10 = __uint_as_float(tf32r(v10));
                v11 = __uint_as_float(tf32r(v11));
            }
            float2 o0 = { v00, v01 };
            float2 o1 = { v10, v11 };
            *reinterpret_cast<float2*>(Cb + r0 * (long)Ncols + c0)       = o0;
            *reinterpret_cast<float2*>(Cb + (r0 + 8) * (long)Ncols + c0) = o1;
        }
    }
}

// ======================= fused dual softmax ==================================
__device__ __forceinline__ float warpMaxF(float v){
#pragma unroll
    for (int o = 16; o; o >>= 1) v = fmaxf(v, __shfl_xor_sync(0xffffffffu, v, o));
    return v;
}
__device__ __forceinline__ float warpMinF(float v){
#pragma unroll
    for (int o = 16; o; o >>= 1) v = fminf(v, __shfl_xor_sync(0xffffffffu, v, o));
    return v;
}
__device__ __forceinline__ float warpSumF(float v){
#pragma unroll
    for (int o = 16; o; o >>= 1) v += __shfl_xor_sync(0xffffffffu, v, o);
    return v;
}

__global__ __launch_bounds__(256)
void attn_softmax_kernel(const float* __restrict__ e,
                         const int* __restrict__ linkage,
                         float* __restrict__ attn)
{
    const int l = blockIdx.x;
    const int b = blockIdx.y;
    const float* row = e + ((long)b * LOW + l) * HIGH;
    const int*   lk  = linkage + (long)l * HIGH;
    float* orow      = attn + ((long)b * LOW + l) * HIGH;

    const int tid  = threadIdx.x;
    const int lane = tid & 31;
    const int wid  = tid >> 5;

    float v[16];
    int   mk[16];
#pragma unroll
    for (int i = 0; i < 16; i++) {
        int h = tid + i * 256;
        v[i]  = row[h];
        mk[i] = lk[h];
    }

    float gmax = -INFINITY, mn = BIGC, mx = -BIGC;
#pragma unroll
    for (int i = 0; i < 16; i++) {
        gmax = fmaxf(gmax, v[i]);
        if (mk[i] > 0) { mn = fminf(mn, v[i]); mx = fmaxf(mx, v[i]); }
    }
    __shared__ float s0[8], s1[8], s2[8];
    gmax = warpMaxF(gmax); mn = warpMinF(mn); mx = warpMaxF(mx);
    if (lane == 0) { s0[wid] = gmax; s1[wid] = mn; s2[wid] = mx; }
    __syncthreads();
    gmax = -INFINITY; mn = BIGC; mx = -BIGC;
#pragma unroll
    for (int w = 0; w < 8; w++) {
        gmax = fmaxf(gmax, s0[w]); mn = fminf(mn, s1[w]); mx = fmaxf(mx, s2[w]);
    }
    __syncthreads();

    float den = mx - mn;
    if (den == 0.0f) den = 1e-6f;
    const bool any = (mn <= mx);
    const float lmax = any ? (mx - mn) / den : -BIGC;

    float ge[16], le[16];
    float gsum = 0.f, lsum = 0.f;
#pragma unroll
    for (int i = 0; i < 16; i++) {
        ge[i] = expf(v[i] - gmax);
        gsum += ge[i];
        float loc = (mk[i] > 0) ? (v[i] - mn) / den : -BIGC;
        le[i] = expf(loc - lmax);
        lsum += le[i];
    }
    gsum = warpSumF(gsum); lsum = warpSumF(lsum);
    if (lane == 0) { s0[wid] = gsum; s1[wid] = lsum; }
    __syncthreads();
    gsum = 0.f; lsum = 0.f;
#pragma unroll
    for (int w = 0; w < 8; w++) { gsum += s0[w]; lsum += s1[w]; }

    const float gi = 1.0f / gsum;
    const float li = 1.0f / lsum;
#pragma unroll
    for (int i = 0; i < 16; i++)
        orow[tid + i * 256] = __uint_as_float(tf32r(ge[i] * gi + le[i] * li));
}

// ======================= launch ==============================================
extern "C" void kernel_launch(void* const* d_in, const int* in_sizes, int n_in,
                              void* d_out, int out_size)
{
    const float* inputs = (const float*)d_in[0];
    const int*   linkage= (const int*)  d_in[1];
    const float* wq_w   = (const float*)d_in[2];
    const float* wq_b   = (const float*)d_in[3];
    const float* wk_w   = (const float*)d_in[4];
    const float* wk_b   = (const float*)d_in[5];
    const float* wv_w   = (const float*)d_in[6];
    const float* wv_b   = (const float*)d_in[7];
    const float* o_w    = (const float*)d_in[8];
    const float* o_b    = (const float*)d_in[9];
    float* out = (float*)d_out;

    float *Q, *K, *V, *E, *Aat, *X, *RI, *Wq, *Wk, *Wv, *Wo;
    cudaGetSymbolAddress((void**)&Q,   g_Q);
    cudaGetSymbolAddress((void**)&K,   g_K);
    cudaGetSymbolAddress((void**)&V,   g_V);
    cudaGetSymbolAddress((void**)&E,   g_E);
    cudaGetSymbolAddress((void**)&Aat, g_A);
    cudaGetSymbolAddress((void**)&X,   g_X);
    cudaGetSymbolAddress((void**)&RI,  g_RI);
    cudaGetSymbolAddress((void**)&Wq,  g_Wq);
    cudaGetSymbolAddress((void**)&Wk,  g_Wk);
    cudaGetSymbolAddress((void**)&Wv,  g_Wv);
    cudaGetSymbolAddress((void**)&Wo,  g_Wo);

    cudaFuncSetAttribute(mm_tc<false,false>,
                         cudaFuncAttributeMaxDynamicSharedMemorySize, SMEM_BYTES);
    cudaFuncSetAttribute(mm_tc<true,true>,
                         cudaFuncAttributeMaxDynamicSharedMemorySize, SMEM_BYTES);
    cudaFuncSetAttribute(mm_tc<false,true>,
                         cudaFuncAttributeMaxDynamicSharedMemorySize, SMEM_BYTES);

    // ---- pre-round inputs + weights to tf32 grid (rna) ----
    {
        long n;
        n = (long)BN*LOW/4;    round_kernel<<<(n+255)/256, 256>>>(inputs, RI, n);
        n = (long)LOW*LOW/4;   round_kernel<<<(n+255)/256, 256>>>(wq_w,  Wq, n);
        n = (long)HIGH*LOW/4;  round_kernel<<<(n+255)/256, 256>>>(wk_w,  Wk, n);
        n = (long)LOW*LOW/4;   round_kernel<<<(n+255)/256, 256>>>(wv_w,  Wv, n);
        n = (long)HIGH*HIGH/4; round_kernel<<<(n+255)/256, 256>>>(o_w,   Wo, n);
    }

    // Q = RI @ Wq^T + wq_b   [16384,512]  (rounded output)
    mm_tc<false,false><<<dim3(LOW/TN, BN/TM, 1), 512, SMEM_BYTES>>>(
        RI, Wq, wq_b, Q, LOW, LOW, 0, 0, 0, LOW, LOW, 1.0f, 1);

    // K = RI @ Wk^T + wk_b   [16384,4096] (rounded)
    mm_tc<false,false><<<dim3(HIGH/TN, BN/TM, 1), 512, SMEM_BYTES>>>(
        RI, Wk, wk_b, K, HIGH, LOW, 0, 0, 0, LOW, LOW, 1.0f, 1);

    // V = RI @ Wv^T + wv_b   [16384,512]  (rounded)
    mm_tc<false,false><<<dim3(LOW/TN, BN/TM, 1), 512, SMEM_BYTES>>>(
        RI, Wv, wv_b, V, LOW, LOW, 0, 0, 0, LOW, LOW, 1.0f, 1);

    // e[b] = (Q[b]^T @ K[b]) / 64   [8,512,4096], contraction over n=2048
    // A(l, n) = Q[n*LOW + l] (MN-major), B(h, n) = K[n*HIGH + h] (MN-major)
    mm_tc<true,true><<<dim3(HIGH/TN, LOW/TM, BB), 512, SMEM_BYTES>>>(
        Q, K, nullptr, E, HIGH, NN,
        (long)NN*LOW, (long)NN*HIGH, (long)LOW*HIGH, LOW, HIGH, 1.0f/64.0f, 0);

    // attn = softmax_global(e) + softmax_local(minmaxnorm(e, mask)), rounded
    attn_softmax_kernel<<<dim3(LOW, BB), 256>>>(E, linkage, Aat);

    // x[b] = V[b] @ attn[b]   [8,2048,4096]; B(h, l) = attn[l*HIGH + h] (MN)
    mm_tc<false,true><<<dim3(HIGH/TN, NN/TM, BB), 512, SMEM_BYTES>>>(
        V, Aat, nullptr, X, HIGH, LOW,
        (long)NN*LOW, (long)LOW*HIGH, (long)NN*HIGH, LOW, HIGH, 1.0f, 1);

    // out = x @ Wo^T + o_b    [16384,4096]
    mm_tc<false,false><<<dim3(HIGH/TN, BN/TM, 1), 512, SMEM_BYTES>>>(
        X, Wo, o_b, out, HIGH, HIGH, 0, 0, 0, HIGH, HIGH, 1.0f, 0);
}